// round 17
// baseline (speedup 1.0000x reference)
#include <cuda_runtime.h>
#include <cuda_bf16.h>

// Problem geometry (fixed by the dataset).
static constexpr int Dv = 160;
static constexpr int Hv = 192;
static constexpr int Wv = 160;
static constexpr int SH = Wv;           // stride of one h-row
static constexpr int SD = Hv * Wv;      // stride of one d-slice (30720)
static constexpr int V  = Dv * Hv * Wv; // 4,915,200 voxels

// Tiling: 8x8x8 voxels per block; halo 6 below / +15 above per axis.
static constexpr int TS  = 8;
static constexpr int HLO = 6;
static constexpr int TW  = 22;              // 6 + 8 + 8 storage span
static constexpr int TA  = TW * TW;         // 484
static constexpr int TN  = TW * TW * TW;    // 10648 floats = 42592 B smem

// Affine fold constants (double-evaluated, rounded to fp32).
// Stage B:  j = (coord + of*rf) * (S/(S-1)) - 0.5
static constexpr float CW = (float)(160.0 / 159.0);
static constexpr float CH = (float)(192.0 / 191.0);
static constexpr float CD = (float)(160.0 / 159.0);
// Stage A:  i = ((g+1)*S - 1) * 0.5 = g*(S/2) + (S-1)/2
static constexpr float AW = 80.0f,  BW = 79.5f;
static constexpr float AH = 96.0f,  BH = 95.5f;
static constexpr float AD = 80.0f,  BD = 79.5f;

// ---------------------------------------------------------------------------
// Global-memory trilinear sample of src, zeros padding. Rare fallback path
// (jitter escaped the SMEM halo). Reference-equivalent clamp+mask form.
// ---------------------------------------------------------------------------
__device__ __noinline__ float samp_src_slow(const float* __restrict__ v,
                                            float ix, float iy, float iz) {
    float xf = floorf(ix), yf = floorf(iy), zf = floorf(iz);
    float tx = ix - xf,    ty = iy - yf,    tz = iz - zf;
    int   x0 = (int)xf,    y0 = (int)yf,    z0 = (int)zf;

    float wx0 = 1.0f - tx, wy0 = 1.0f - ty, wz0 = 1.0f - tz;
    float a = wz0 * wy0, b = wz0 * ty, c = tz * wy0, e = tz * ty;

    bool bx0 = (unsigned)x0       < (unsigned)Wv;
    bool bx1 = (unsigned)(x0 + 1) < (unsigned)Wv;
    bool by0 = (unsigned)y0       < (unsigned)Hv;
    bool by1 = (unsigned)(y0 + 1) < (unsigned)Hv;
    bool bz0 = (unsigned)z0       < (unsigned)Dv;
    bool bz1 = (unsigned)(z0 + 1) < (unsigned)Dv;

    int cx0 = min(max(x0,     0), Wv - 1), cx1 = min(max(x0 + 1, 0), Wv - 1);
    int cy0 = min(max(y0,     0), Hv - 1), cy1 = min(max(y0 + 1, 0), Hv - 1);
    int cz0 = min(max(z0,     0), Dv - 1), cz1 = min(max(z0 + 1, 0), Dv - 1);

    float acc = 0.0f;
    acc += v[(cz0 * Hv + cy0) * Wv + cx0] * ((a * wx0) * ((bz0 & by0 & bx0) ? 1.0f : 0.0f));
    acc += v[(cz0 * Hv + cy0) * Wv + cx1] * ((a * tx ) * ((bz0 & by0 & bx1) ? 1.0f : 0.0f));
    acc += v[(cz0 * Hv + cy1) * Wv + cx0] * ((b * wx0) * ((bz0 & by1 & bx0) ? 1.0f : 0.0f));
    acc += v[(cz0 * Hv + cy1) * Wv + cx1] * ((b * tx ) * ((bz0 & by1 & bx1) ? 1.0f : 0.0f));
    acc += v[(cz1 * Hv + cy0) * Wv + cx0] * ((c * wx0) * ((bz1 & by0 & bx0) ? 1.0f : 0.0f));
    acc += v[(cz1 * Hv + cy0) * Wv + cx1] * ((c * tx ) * ((bz1 & by0 & bx1) ? 1.0f : 0.0f));
    acc += v[(cz1 * Hv + cy1) * Wv + cx0] * ((e * wx0) * ((bz1 & by1 & bx0) ? 1.0f : 0.0f));
    acc += v[(cz1 * Hv + cy1) * Wv + cx1] * ((e * tx ) * ((bz1 & by1 & bx1) ? 1.0f : 0.0f));
    return acc;
}

// ---------------------------------------------------------------------------
// SMEM-tile trilinear sample. The tile holds src over
// [bx, bx+TW) x [by, by+TW) x [bz, bz+TW) with zeros where outside the image,
// so zero-padding falls out for free (0 * weight). Falls back to the global
// path only when a corner escapes the tile.
// ---------------------------------------------------------------------------
__device__ __forceinline__ float samp_tile(const float* __restrict__ tile,
                                           const float* __restrict__ src,
                                           float jx, float jy, float jz,
                                           int bx, int by, int bz) {
    float xf = floorf(jx), yf = floorf(jy), zf = floorf(jz);
    float tx = jx - xf,    ty = jy - yf,    tz = jz - zf;
    int   lx = (int)xf - bx, ly = (int)yf - by, lz = (int)zf - bz;

    float wx0 = 1.0f - tx, wy0 = 1.0f - ty, wz0 = 1.0f - tz;
    float a = wz0 * wy0;   // z0,y0
    float b = wz0 * ty;    // z0,y1
    float c = tz  * wy0;   // z1,y0
    float e = tz  * ty;    // z1,y1

    // Need corner+1 inside the tile: l in [0, TW-2] on every axis.
    if (((unsigned)lx < (unsigned)(TW - 1)) &
        ((unsigned)ly < (unsigned)(TW - 1)) &
        ((unsigned)lz < (unsigned)(TW - 1))) {
        const float* q = tile + (lz * TW + ly) * TW + lx;
        float acc;
        acc  = q[0]           * (a * wx0);
        acc += q[1]           * (a * tx );
        acc += q[TW]          * (b * wx0);
        acc += q[TW + 1]      * (b * tx );
        acc += q[TA]          * (c * wx0);
        acc += q[TA + 1]      * (c * tx );
        acc += q[TA + TW]     * (e * wx0);
        acc += q[TA + TW + 1] * (e * tx );
        return acc;
    }
    return samp_src_slow(src, jx, jy, jz);
}

// ---------------------------------------------------------------------------
// Trilinear sample of the 3-channel flow1 volume, zeros padding. The
// reference feeds RAW voxel coordinates through the [-1,1] unnormalizer, so
// this is fully out of bounds for essentially every voxel. Caller does the
// cheap fully-out test; this is the rare slow path.
// ---------------------------------------------------------------------------
__device__ __noinline__ void samp_flow(const float* __restrict__ f,
                                       float ix, float iy, float iz,
                                       float& o0, float& o1, float& o2) {
    float xf = floorf(ix), yf = floorf(iy), zf = floorf(iz);
    int   x0 = (int)xf,    y0 = (int)yf,    z0 = (int)zf;

    float tx = ix - xf, ty = iy - yf, tz = iz - zf;
    float wx0 = 1.0f - tx, wy0 = 1.0f - ty, wz0 = 1.0f - tz;
    float a = wz0 * wy0, b = wz0 * ty, c = tz * wy0, e = tz * ty;

    bool bx0 = (unsigned)x0       < (unsigned)Wv;
    bool bx1 = (unsigned)(x0 + 1) < (unsigned)Wv;
    bool by0 = (unsigned)y0       < (unsigned)Hv;
    bool by1 = (unsigned)(y0 + 1) < (unsigned)Hv;
    bool bz0 = (unsigned)z0       < (unsigned)Dv;
    bool bz1 = (unsigned)(z0 + 1) < (unsigned)Dv;

    int cx0 = min(max(x0,     0), Wv - 1), cx1 = min(max(x0 + 1, 0), Wv - 1);
    int cy0 = min(max(y0,     0), Hv - 1), cy1 = min(max(y0 + 1, 0), Hv - 1);
    int cz0 = min(max(z0,     0), Dv - 1), cz1 = min(max(z0 + 1, 0), Dv - 1);

    int   idx[8];
    float wgt[8];
    idx[0] = (cz0 * Hv + cy0) * Wv + cx0; wgt[0] = (a * wx0) * ((bz0 & by0 & bx0) ? 1.0f : 0.0f);
    idx[1] = (cz0 * Hv + cy0) * Wv + cx1; wgt[1] = (a * tx ) * ((bz0 & by0 & bx1) ? 1.0f : 0.0f);
    idx[2] = (cz0 * Hv + cy1) * Wv + cx0; wgt[2] = (b * wx0) * ((bz0 & by1 & bx0) ? 1.0f : 0.0f);
    idx[3] = (cz0 * Hv + cy1) * Wv + cx1; wgt[3] = (b * tx ) * ((bz0 & by1 & bx1) ? 1.0f : 0.0f);
    idx[4] = (cz1 * Hv + cy0) * Wv + cx0; wgt[4] = (c * wx0) * ((bz1 & by0 & bx0) ? 1.0f : 0.0f);
    idx[5] = (cz1 * Hv + cy0) * Wv + cx1; wgt[5] = (c * tx ) * ((bz1 & by0 & bx1) ? 1.0f : 0.0f);
    idx[6] = (cz1 * Hv + cy1) * Wv + cx0; wgt[6] = (e * wx0) * ((bz1 & by1 & bx0) ? 1.0f : 0.0f);
    idx[7] = (cz1 * Hv + cy1) * Wv + cx1; wgt[7] = (e * tx ) * ((bz1 & by1 & bx1) ? 1.0f : 0.0f);

    float s0 = 0.f, s1 = 0.f, s2 = 0.f;
#pragma unroll
    for (int k = 0; k < 8; k++) {
        float wk = wgt[k];
        int   ik = idx[k];
        s0 += f[ik]         * wk;
        s1 += f[V + ik]     * wk;
        s2 += f[2 * V + ik] * wk;
    }
    o0 = s0; o1 = s1; o2 = s2;
}

// ---------------------------------------------------------------------------
// Stage A + out_flow for one voxel.
// ---------------------------------------------------------------------------
__device__ __forceinline__ void stage_a(const float* __restrict__ flow1,
                                        float fw_, float fh_, float fd_,
                                        float f2d, float f2h, float f2w, float rf,
                                        float& ofd, float& ofh, float& ofw) {
    float gz = fmaf(f2d, rf, fd_);
    float gy = fmaf(f2h, rf, fh_);
    float gx = fmaf(f2w, rf, fw_);

    float ix = fmaf(gx, AW, BW);
    float iy = fmaf(gy, AH, BH);
    float iz = fmaf(gz, AD, BD);

    float a0 = 0.f, a1 = 0.f, a2 = 0.f;
    if (!(ix < -1.0f || ix >= (float)Wv ||
          iy < -1.0f || iy >= (float)Hv ||
          iz < -1.0f || iz >= (float)Dv))
        samp_flow(flow1, ix, iy, iz, a0, a1, a2);

    ofd = a0 + f2d;
    ofh = a1 + f2h;
    ofw = a2 + f2w;
}

// ---------------------------------------------------------------------------
// Tiled fused kernel. Grid (20, 24, 20) of 8x8x8 voxel tiles; 256 threads,
// each owning 2 consecutive-x voxels. The 22^3 src halo tile (zeros outside
// the image) is staged in SMEM with coalesced loads; gathers hit the SMEM
// crossbar instead of generating divergent L1 wavefronts (the measured
// roofline of the direct-gather kernels, ~4.5 wf/voxel).
//   out[0 : V ) = deform_2_img
//   out[V : 2V) = out_flow ch0 (d)
//   out[2V: 3V) = out_flow ch1 (h)
//   out[3V: 4V) = out_flow ch2 (w)
// ---------------------------------------------------------------------------
__global__ void __launch_bounds__(256, 5)
spatial_transformer_tile(const float* __restrict__ src,
                         const float* __restrict__ flow1,
                         const float* __restrict__ flow2,
                         const float* __restrict__ rf_ptr,
                         float* __restrict__ out) {
    __shared__ float tile[TN];

    const float rf = __ldg(rf_ptr);
    const int tid = threadIdx.x;

    const int ox = blockIdx.x * TS;
    const int oy = blockIdx.y * TS;
    const int oz = blockIdx.z * TS;

    const int lxp = tid & 3;          // x-pair index: gx = ox + 2*lxp
    const int ly  = (tid >> 2) & 7;
    const int lz  = tid >> 5;

    const int gx = ox + 2 * lxp;
    const int gy = oy + ly;
    const int gz = oz + lz;
    const int p  = (gz * Hv + gy) * Wv + gx;   // even -> float2-aligned

    const float fw_ = (float)gx;
    const float fh_ = (float)gy;
    const float fd_ = (float)gz;

    // ---- flow2 loads + stage A + retire out_flow stores early.
    float2 F2d = *reinterpret_cast<const float2*>(flow2 + p);
    float2 F2h = *reinterpret_cast<const float2*>(flow2 + V + p);
    float2 F2w = *reinterpret_cast<const float2*>(flow2 + 2 * V + p);

    float ofd0, ofh0, ofw0, ofd1, ofh1, ofw1;
    stage_a(flow1, fw_,        fh_, fd_, F2d.x, F2h.x, F2w.x, rf, ofd0, ofh0, ofw0);
    stage_a(flow1, fw_ + 1.0f, fh_, fd_, F2d.y, F2h.y, F2w.y, rf, ofd1, ofh1, ofw1);

    *reinterpret_cast<float2*>(out + V + p)     = make_float2(ofd0, ofd1);
    *reinterpret_cast<float2*>(out + 2 * V + p) = make_float2(ofh0, ofh1);
    *reinterpret_cast<float2*>(out + 3 * V + p) = make_float2(ofw0, ofw1);

    // ---- Cooperative halo-tile load (zeros outside the image).
    const int bx = ox - HLO, by = oy - HLO, bz = oz - HLO;
    for (int i = tid; i < TN; i += 256) {
        int zz  = i / TA;
        int rem = i - zz * TA;
        int yy  = rem / TW;
        int xx  = rem - yy * TW;
        int X = bx + xx, Y = by + yy, Z = bz + zz;
        float val = 0.0f;
        if (((unsigned)X < (unsigned)Wv) &
            ((unsigned)Y < (unsigned)Hv) &
            ((unsigned)Z < (unsigned)Dv))
            val = __ldg(src + (Z * Hv + Y) * Wv + X);
        tile[i] = val;
    }
    __syncthreads();

    // ---- Stage B: folded affine  j = (coord + of*rf) * S/(S-1) - 0.5,
    // then trilinear gather from the SMEM tile.
    float jz0 = fmaf(fmaf(ofd0, rf, fd_), CD, -0.5f);
    float jy0 = fmaf(fmaf(ofh0, rf, fh_), CH, -0.5f);
    float jx0 = fmaf(fmaf(ofw0, rf, fw_), CW, -0.5f);
    float jz1 = fmaf(fmaf(ofd1, rf, fd_), CD, -0.5f);
    float jy1 = fmaf(fmaf(ofh1, rf, fh_), CH, -0.5f);
    float jx1 = fmaf(fmaf(ofw1, rf, fw_ + 1.0f), CW, -0.5f);

    float img0 = samp_tile(tile, src, jx0, jy0, jz0, bx, by, bz);
    float img1 = samp_tile(tile, src, jx1, jy1, jz1, bx, by, bz);

    *reinterpret_cast<float2*>(out + p) = make_float2(img0, img1);
}

extern "C" void kernel_launch(void* const* d_in, const int* in_sizes, int n_in,
                              void* d_out, int out_size) {
    // metadata order: src, flow1, flow2, grid (unused: analytic meshgrid),
    // range_flow (device scalar).
    const float* src   = (const float*)d_in[0];
    const float* flow1 = (const float*)d_in[1];
    const float* flow2 = (const float*)d_in[2];
    const float* rf    = (const float*)d_in[4];
    float* out = (float*)d_out;

    dim3 grid(Wv / TS, Hv / TS, Dv / TS);   // (20, 24, 20)
    spatial_transformer_tile<<<grid, 256>>>(src, flow1, flow2, rf, out);
}